// round 1
// baseline (speedup 1.0000x reference)
#include <cuda_runtime.h>
#include <cstdint>

// SparseToDense: out[b][f][x][y][z] += feats[n][f] for each point n with
// coords (b,x,y,z), x,y,z in [0,128). Output (4,16,128,128,128) fp32.

#define VOL   (128 * 128 * 128)   // 2097152 voxels per (batch, feat) plane
#define FEATS 16

__global__ void __launch_bounds__(256)
sparse_scatter_kernel(const int4* __restrict__ coords,
                      const float4* __restrict__ feats,
                      float* __restrict__ out,
                      int n)
{
    int i = blockIdx.x * blockDim.x + threadIdx.x;
    if (i >= n) return;

    const int4 c = __ldg(&coords[i]);
    // coords are non-negative; unsigned compare handles both bounds
    const unsigned x = (unsigned)c.y;
    const unsigned y = (unsigned)c.z;
    const unsigned z = (unsigned)c.w;
    if ((x >= 128u) | (y >= 128u) | (z >= 128u)) return;

    const unsigned lin = (x << 14) | (y << 7) | z;           // x*128*128 + y*128 + z
    float* base = out + (size_t)c.x * (FEATS * (size_t)VOL) + lin;

    const float4* fp = feats + (size_t)i * 4;
    float4 f0 = __ldg(fp + 0);
    float4 f1 = __ldg(fp + 1);
    float4 f2 = __ldg(fp + 2);
    float4 f3 = __ldg(fp + 3);

    float v[16] = { f0.x, f0.y, f0.z, f0.w,
                    f1.x, f1.y, f1.z, f1.w,
                    f2.x, f2.y, f2.z, f2.w,
                    f3.x, f3.y, f3.z, f3.w };

    #pragma unroll
    for (int k = 0; k < 16; k++) {
        // fire-and-forget reduction (REDG), no return value
        asm volatile("red.global.add.f32 [%0], %1;"
                     :: "l"(base + (size_t)k * VOL), "f"(v[k])
                     : "memory");
    }
}

extern "C" void kernel_launch(void* const* d_in, const int* in_sizes, int n_in,
                              void* d_out, int out_size)
{
    const int4*   coords = (const int4*)d_in[0];   // (N,4) int32: b,x,y,z
    const float4* feats  = (const float4*)d_in[1]; // (N,16) float32
    float*        out    = (float*)d_out;          // (4,16,128,128,128) float32

    const int n = in_sizes[0] / 4;

    // Zero the poisoned output (memset node is graph-capturable)
    cudaMemsetAsync(d_out, 0, (size_t)out_size * sizeof(float));

    const int threads = 256;
    const int blocks  = (n + threads - 1) / threads;
    sparse_scatter_kernel<<<blocks, threads>>>(coords, feats, out, n);
}

// round 2
// speedup vs baseline: 2.1705x; 2.1705x over previous
#include <cuda_runtime.h>
#include <cstdint>

// SparseToDense with counting-sort-by-spatial-bin to make the scatter atomics
// L2-resident. out[b][f][x][y][z] += feats[n][f], out = (4,16,128,128,128) f32.

#define VOL    (128 * 128 * 128)
#define FEATS  16
#define NBINS  4096
#define NMAX   2100000

__device__ int g_bins[NBINS];
__device__ int g_cursor[NBINS];
__device__ int g_total;
__device__ int g_order[NMAX];

__device__ __forceinline__ bool point_bin(const int4 c, unsigned& bin, unsigned& lin)
{
    const unsigned x = (unsigned)c.y;
    const unsigned y = (unsigned)c.z;
    const unsigned z = (unsigned)c.w;
    if ((x >= 128u) | (y >= 128u) | (z >= 128u)) return false;
    lin = (x << 14) | (y << 7) | z;
    bin = ((((unsigned)c.x << 7) | x) << 3) | (y >> 4);   // (b,x,y/16) -> [0,4096)
    return true;
}

__global__ void zero_bins_kernel()
{
    int i = blockIdx.x * blockDim.x + threadIdx.x;
    if (i < NBINS) g_bins[i] = 0;
}

__global__ void __launch_bounds__(256)
hist_kernel(const int4* __restrict__ coords, int n)
{
    __shared__ int sh[NBINS];
    for (int i = threadIdx.x; i < NBINS; i += blockDim.x) sh[i] = 0;
    __syncthreads();

    for (int i = blockIdx.x * blockDim.x + threadIdx.x; i < n;
         i += gridDim.x * blockDim.x) {
        const int4 c = __ldg(&coords[i]);
        unsigned bin, lin;
        if (point_bin(c, bin, lin)) atomicAdd(&sh[bin], 1);
    }
    __syncthreads();
    for (int i = threadIdx.x; i < NBINS; i += blockDim.x)
        if (sh[i]) atomicAdd(&g_bins[i], sh[i]);
}

__global__ void scan_kernel()
{
    __shared__ int s[1024];
    const int t = threadIdx.x;
    const int v0 = g_bins[4*t + 0];
    const int v1 = g_bins[4*t + 1];
    const int v2 = g_bins[4*t + 2];
    const int v3 = g_bins[4*t + 3];
    const int sum = v0 + v1 + v2 + v3;
    s[t] = sum;
    __syncthreads();
    for (int off = 1; off < 1024; off <<= 1) {
        int x = (t >= off) ? s[t - off] : 0;
        __syncthreads();
        s[t] += x;
        __syncthreads();
    }
    const int incl = s[t];
    const int excl = incl - sum;
    g_cursor[4*t + 0] = excl;
    g_cursor[4*t + 1] = excl + v0;
    g_cursor[4*t + 2] = excl + v0 + v1;
    g_cursor[4*t + 3] = excl + v0 + v1 + v2;
    if (t == 1023) g_total = incl;
}

__global__ void __launch_bounds__(256)
reorder_kernel(const int4* __restrict__ coords, int n)
{
    for (int i = blockIdx.x * blockDim.x + threadIdx.x; i < n;
         i += gridDim.x * blockDim.x) {
        const int4 c = __ldg(&coords[i]);
        unsigned bin, lin;
        if (point_bin(c, bin, lin)) {
            int pos = atomicAdd(&g_cursor[bin], 1);
            g_order[pos] = i;
        }
    }
}

__global__ void __launch_bounds__(256)
scatter_kernel(const int4* __restrict__ coords,
               const float4* __restrict__ feats,
               float* __restrict__ out)
{
    const int t = blockIdx.x * blockDim.x + threadIdx.x;
    if (t >= g_total) return;
    const int i = g_order[t];

    const int4 c = __ldg(&coords[i]);
    const unsigned lin = ((unsigned)c.y << 14) | ((unsigned)c.z << 7) | (unsigned)c.w;
    float* base = out + (size_t)c.x * (FEATS * (size_t)VOL) + lin;

    const float4* fp = feats + (size_t)i * 4;
    float4 f0 = __ldg(fp + 0);
    float4 f1 = __ldg(fp + 1);
    float4 f2 = __ldg(fp + 2);
    float4 f3 = __ldg(fp + 3);

    float v[16] = { f0.x, f0.y, f0.z, f0.w,
                    f1.x, f1.y, f1.z, f1.w,
                    f2.x, f2.y, f2.z, f2.w,
                    f3.x, f3.y, f3.z, f3.w };

    #pragma unroll
    for (int k = 0; k < 16; k++) {
        asm volatile("red.global.add.f32 [%0], %1;"
                     :: "l"(base + (size_t)k * VOL), "f"(v[k])
                     : "memory");
    }
}

extern "C" void kernel_launch(void* const* d_in, const int* in_sizes, int n_in,
                              void* d_out, int out_size)
{
    const int4*   coords = (const int4*)d_in[0];
    const float4* feats  = (const float4*)d_in[1];
    float*        out    = (float*)d_out;

    const int n = in_sizes[0] / 4;
    const int threads = 256;
    const int blocks  = (n + threads - 1) / threads;

    cudaMemsetAsync(d_out, 0, (size_t)out_size * sizeof(float));
    zero_bins_kernel<<<(NBINS + 255) / 256, 256>>>();
    hist_kernel<<<1024, threads>>>(coords, n);
    scan_kernel<<<1, 1024>>>();
    reorder_kernel<<<1024, threads>>>(coords, n);
    scatter_kernel<<<blocks, threads>>>(coords, feats, out);
}

// round 3
// speedup vs baseline: 4.1424x; 1.9085x over previous
#include <cuda_runtime.h>
#include <cstdint>

// SparseToDense via counting sort to (b,x,y/4) bins + per-CTA exclusive smem
// accumulation. out[b][f][x][y][z] += feats[n][f], out = (4,16,128,128,128) f32.
// No output memset, no global atomics in the hot phase.

#define VOL      (128 * 128 * 128)
#define FEATS    16
#define NBINS    16384          // 4 batches * 128 x * 32 y-groups (y/4)
#define NMAX     2100000
#define REGION   (4 * 128 * FEATS)   // floats per bin region = 8192 (32KB)

__device__ int g_bins[NBINS];
__device__ int g_cursor[NBINS];
__device__ int g_start[NBINS + 1];
__device__ unsigned g_order[NMAX];   // packed: (point_idx << 9) | local_voxel

__device__ __forceinline__ bool decode(const int4 c, unsigned& bin, unsigned& local)
{
    const unsigned x = (unsigned)c.y;
    const unsigned y = (unsigned)c.z;
    const unsigned z = (unsigned)c.w;
    if ((x >= 128u) | (y >= 128u) | (z >= 128u)) return false;
    bin   = ((((unsigned)c.x << 7) | x) << 5) | (y >> 2);   // (b,x,y/4)
    local = ((y & 3u) << 7) | z;                            // 0..511
    return true;
}

__global__ void zero_bins_kernel()
{
    int i = blockIdx.x * blockDim.x + threadIdx.x;
    if (i < NBINS) g_bins[i] = 0;
}

__global__ void __launch_bounds__(256)
hist_kernel(const int4* __restrict__ coords, int n)
{
    for (int i = blockIdx.x * blockDim.x + threadIdx.x; i < n;
         i += gridDim.x * blockDim.x) {
        unsigned bin, local;
        if (decode(__ldg(&coords[i]), bin, local))
            atomicAdd(&g_bins[bin], 1);
    }
}

__global__ void scan_kernel()
{
    __shared__ int s[1024];
    const int t = threadIdx.x;
    int v[16];
    int sum = 0;
    #pragma unroll
    for (int k = 0; k < 16; k++) { v[k] = g_bins[t * 16 + k]; sum += v[k]; }
    s[t] = sum;
    __syncthreads();
    for (int off = 1; off < 1024; off <<= 1) {
        int x = (t >= off) ? s[t - off] : 0;
        __syncthreads();
        s[t] += x;
        __syncthreads();
    }
    int run = s[t] - sum;     // exclusive prefix of this thread's 16 bins
    #pragma unroll
    for (int k = 0; k < 16; k++) {
        g_start[t * 16 + k]  = run;
        g_cursor[t * 16 + k] = run;
        run += v[k];
    }
    if (t == 1023) g_start[NBINS] = run;
}

__global__ void __launch_bounds__(256)
reorder_kernel(const int4* __restrict__ coords, int n)
{
    for (int i = blockIdx.x * blockDim.x + threadIdx.x; i < n;
         i += gridDim.x * blockDim.x) {
        unsigned bin, local;
        if (decode(__ldg(&coords[i]), bin, local)) {
            int pos = atomicAdd(&g_cursor[bin], 1);
            g_order[pos] = ((unsigned)i << 9) | local;
        }
    }
}

// One CTA per bin: zero 32KB smem, accumulate owned points, stream region out.
__global__ void __launch_bounds__(256)
scatter_kernel(const float4* __restrict__ feats, float* __restrict__ out)
{
    __shared__ float acc[REGION];               // layout [f][4y][128z]
    const unsigned bin = blockIdx.x;
    const int tid = threadIdx.x;

    #pragma unroll
    for (int k = 0; k < REGION / 4 / 256; k++)
        *(float4*)&acc[(k * 256 + tid) * 4] = make_float4(0.f, 0.f, 0.f, 0.f);
    __syncthreads();

    const int start = g_start[bin];
    const int end   = g_start[bin + 1];

    for (int t = start + tid; t < end; t += 256) {
        const unsigned pay   = g_order[t];
        const unsigned local = pay & 511u;
        const unsigned i     = pay >> 9;

        const float4* fp = feats + (size_t)i * 4;
        float4 f0 = __ldg(fp + 0);
        float4 f1 = __ldg(fp + 1);
        float4 f2 = __ldg(fp + 2);
        float4 f3 = __ldg(fp + 3);
        float v[16] = { f0.x, f0.y, f0.z, f0.w,
                        f1.x, f1.y, f1.z, f1.w,
                        f2.x, f2.y, f2.z, f2.w,
                        f3.x, f3.y, f3.z, f3.w };
        #pragma unroll
        for (int f = 0; f < FEATS; f++)
            atomicAdd(&acc[f * 512 + local], v[f]);
    }
    __syncthreads();

    // Writeback: per feat, 512 contiguous floats; whole region = zero-fill + sums
    const unsigned b  = bin >> 12;
    const unsigned x  = (bin >> 5) & 127u;
    const unsigned yg = bin & 31u;
    float* base = out + ((size_t)b * FEATS) * VOL + ((size_t)x << 14) + ((size_t)yg << 9);

    #pragma unroll
    for (int k = 0; k < REGION / 4 / 256; k++) {
        const int idx = k * 256 + tid;          // 0..2047 float4 slots
        const int f   = idx >> 7;               // 128 float4 per feat
        const int w   = idx & 127;
        float4 val = *(const float4*)&acc[(size_t)f * 512 + (size_t)w * 4];
        *(float4*)(base + (size_t)f * VOL + (size_t)w * 4) = val;
    }
}

extern "C" void kernel_launch(void* const* d_in, const int* in_sizes, int n_in,
                              void* d_out, int out_size)
{
    const int4*   coords = (const int4*)d_in[0];
    const float4* feats  = (const float4*)d_in[1];
    float*        out    = (float*)d_out;

    const int n = in_sizes[0] / 4;

    zero_bins_kernel<<<(NBINS + 255) / 256, 256>>>();
    hist_kernel<<<1024, 256>>>(coords, n);
    scan_kernel<<<1, 1024>>>();
    reorder_kernel<<<1024, 256>>>(coords, n);
    scatter_kernel<<<NBINS, 256>>>(feats, out);
}